// round 15
// baseline (speedup 1.0000x reference)
#include <cuda_runtime.h>
#include <cstdint>

typedef unsigned long long ull;

// Problem constants
#define B_  2048
#define T_  512
#define I_  58
#define H_  23
#define G_  69          // 3*H
#define MP_ 29          // k-pairs for x-projection (58/2)
#define TS_ 4           // timesteps per group
#define NG_ (T_/TS_)    // 128 groups
#define XB_ (TS_*I_)    // floats per x buffer (232)
#define XV_ (XB_/4)     // float4 vectors per buffer (58)

// ---------------- f32x2 helpers ----------------
__device__ __forceinline__ ull pk2(float a, float b) {
    ull r;
    asm("mov.b64 %0, {%1, %2};" : "=l"(r) : "f"(a), "f"(b));
    return r;
}
__device__ __forceinline__ void upk2(ull v, float& a, float& b) {
    asm("mov.b64 {%0, %1}, %2;" : "=f"(a), "=f"(b) : "l"(v));
}
__device__ __forceinline__ ull ffma2(ull a, ull b, ull c) {
    ull d;
    asm("fma.rn.f32x2 %0, %1, %2, %3;" : "=l"(d) : "l"(a), "l"(b), "l"(c));
    return d;
}
__device__ __forceinline__ ull add2(ull a, ull b) {
    ull d;
    asm("add.rn.f32x2 %0, %1, %2;" : "=l"(d) : "l"(a), "l"(b));
    return d;
}
// ---------------- fast transcendentals ----------------
__device__ __forceinline__ float fex2(float x) {
    float y; asm("ex2.approx.f32 %0, %1;" : "=f"(y) : "f"(x)); return y;
}
__device__ __forceinline__ float frcp(float x) {
    float y; asm("rcp.approx.f32 %0, %1;" : "=f"(y) : "f"(x)); return y;
}
__device__ __forceinline__ float fsigmoid(float x) {
    return frcp(1.0f + fex2(-1.4426950408889634f * x));
}
__device__ __forceinline__ float ftanh(float x) {
    float e = fex2(2.8853900817779268f * x);
    return fmaf(-2.0f, frcp(e + 1.0f), 1.0f);
}

// ============================================================================
// FUSED kernel: x-projection + GRU scan in one pass.
//   Block = 128 threads = 4 warps = 4 batch rows (1 warp per row).
//   Per 4-step group:
//     - issue LDG.128 prefetch of group g+1 into registers (latency hides
//       under ~1500 cyc of group-g math)
//     - phase A: project 4 steps' x gates (W_ih pairs in smem, lane-indexed)
//     - phase B: scan 4 steps (W_hh in registers, h double-buffered in smem)
//     - store prefetch registers to the other smem buffer, __syncwarp
//   No cp.async, no cross-kernel scratch, no second kernel.
// ============================================================================
__global__ __launch_bounds__(128, 4) void fused_gru_kernel(
    const float* __restrict__ task,   // [B][T][58]
    const float* __restrict__ Wih,    // [69][58]
    const float* __restrict__ Whh,    // [69][23]
    const float* __restrict__ bih,    // [69]
    const float* __restrict__ bhh,    // [69]
    const float* __restrict__ piw,    // [23]
    const float* __restrict__ pib,    // [23]
    float* __restrict__ out_action,   // [B][T][23]
    float* __restrict__ out_hidden)   // [B][23]
{
    // W_ih as k-pairs, lane-indexed: [gate][m][unit(24)] (16.7KB)
    __shared__ __align__(16) ull wih_s[3][MP_][24];
    // x stage: [warp][dbl buf][232 floats] (7.4KB)
    __shared__ __align__(16) float xs[4][2][XB_];
    // h double buffers (+pad slot 23 == 1.0 as b_hh carrier)
    __shared__ __align__(16) float hsm[4][2][32];

    const int tid = threadIdx.x;
    const int j  = tid & 31;
    const int w  = tid >> 5;
    const int b  = blockIdx.x * 4 + w;
    const int jc = (j < H_) ? j : (H_ - 1);
    const bool act = (j < H_);

    // ---- stage W_ih pairs (one-time, block-wide) ----
    for (int i = tid; i < 3 * MP_ * 24; i += 128) {
        int g  = i / (MP_ * 24);
        int rm = i - g * MP_ * 24;
        int m  = rm / 24, jj = rm - 24 * m;
        float w0 = 0.0f, w1 = 0.0f;
        if (jj < H_) {
            w0 = Wih[(g * H_ + jj) * I_ + 2 * m];
            w1 = Wih[(g * H_ + jj) * I_ + 2 * m + 1];
        }
        reinterpret_cast<ull*>(wih_s)[i] = pk2(w0, w1);
    }

    // ---- per-lane scan weights W_hh (12 k-pairs; pad pair carries b_hh) ----
    ull WR[12], WZ[12], WN[12];
    {
        const float* wr = Whh + (size_t)jc * H_;
        const float* wz = Whh + (size_t)(H_ + jc) * H_;
        const float* wn = Whh + (size_t)(2 * H_ + jc) * H_;
        #pragma unroll
        for (int m = 0; m < 11; m++) {
            WR[m] = pk2(wr[2 * m], wr[2 * m + 1]);
            WZ[m] = pk2(wz[2 * m], wz[2 * m + 1]);
            WN[m] = pk2(wn[2 * m], wn[2 * m + 1]);
        }
        WR[11] = pk2(wr[22], bhh[jc]);
        WZ[11] = pk2(wz[22], bhh[H_ + jc]);
        WN[11] = pk2(wn[22], bhh[2 * H_ + jc]);
    }
    // projection bias (accumulator init pairs)
    const ull BXR = pk2(bih[jc], 0.0f);
    const ull BXZ = pk2(bih[H_ + jc], 0.0f);
    const ull BXN = pk2(bih[2 * H_ + jc], 0.0f);
    const float pw = piw[jc], pb = pib[jc];

    // h buffers: zeros + pad slot [23] = 1.0
    {
        float v = (j == 23) ? 1.0f : 0.0f;
        hsm[w][0][j] = v;
        hsm[w][1][j] = v;
    }

    const float* rowsrc = task + (size_t)b * T_ * I_;
    float* outp = out_action + (size_t)b * T_ * H_;
    float4* xbuf0 = reinterpret_cast<float4*>(&xs[w][0][0]);
    float4* xbuf1 = reinterpret_cast<float4*>(&xs[w][1][0]);
    const int c0 = j;          // vector slot 0..31 (always < 58)
    const int c1 = j + 32;     // vector slot 32..63 (valid if < 58)
    const bool has1 = (c1 < XV_);

    // ---- prologue: load group 0 directly into buf 0 ----
    {
        const float4* src = reinterpret_cast<const float4*>(rowsrc);
        xbuf0[c0] = src[c0];
        if (has1) xbuf1[0] = xbuf1[0];            // no-op, keep symmetry
        if (has1) xbuf0[c1] = src[c1];
    }
    __syncthreads();   // wih_s + hsm + buf0 visible

    float h = 0.0f;

    #pragma unroll 1
    for (int g = 0; g < NG_; g++) {
        // ---- prefetch group g+1 into registers (clamped) ----
        float4 pf0, pf1;
        {
            int gn = (g + 1 < NG_) ? g + 1 : NG_ - 1;
            const float4* src =
                reinterpret_cast<const float4*>(rowsrc + (size_t)gn * XB_);
            pf0 = src[c0];
            pf1 = has1 ? src[c1] : make_float4(0.f, 0.f, 0.f, 0.f);
        }

        // ================= Phase A: project 4 steps =================
        const float* xb = xs[w][g & 1];
        ull aR[TS_], aZ[TS_], aN[TS_];
        #pragma unroll
        for (int s = 0; s < TS_; s++) { aR[s] = BXR; aZ[s] = BXZ; aN[s] = BXN; }

        #pragma unroll
        for (int m = 0; m < MP_; m++) {
            ull w_r = wih_s[0][m][jc];     // lane-indexed LDS.64, conflict-free
            ull w_z = wih_s[1][m][jc];
            ull w_n = wih_s[2][m][jc];
            #pragma unroll
            for (int s = 0; s < TS_; s++) {
                ull x2 = *reinterpret_cast<const ull*>(xb + s * I_ + 2 * m);
                aR[s] = ffma2(w_r, x2, aR[s]);
                aZ[s] = ffma2(w_z, x2, aZ[s]);
                aN[s] = ffma2(w_n, x2, aN[s]);
            }
        }
        float xr[TS_], xz[TS_], xn[TS_];
        #pragma unroll
        for (int s = 0; s < TS_; s++) {
            float lo, hi;
            upk2(aR[s], lo, hi); xr[s] = lo + hi;
            upk2(aZ[s], lo, hi); xz[s] = lo + hi;
            upk2(aN[s], lo, hi); xn[s] = lo + hi;
        }

        // ================= Phase B: scan 4 steps =================
        #pragma unroll
        for (int s = 0; s < TS_; s++) {
            const ulonglong2* hq =
                reinterpret_cast<const ulonglong2*>(hsm[w][s & 1]);
            ull aR0 = 0, aR1 = 0, aZ0 = 0, aZ1 = 0, aN0 = 0, aN1 = 0;
            #pragma unroll
            for (int m = 0; m < 6; m++) {
                ulonglong2 q = hq[m];
                aR0 = ffma2(WR[2 * m],     q.x, aR0);
                aR1 = ffma2(WR[2 * m + 1], q.y, aR1);
                aZ0 = ffma2(WZ[2 * m],     q.x, aZ0);
                aZ1 = ffma2(WZ[2 * m + 1], q.y, aZ1);
                aN0 = ffma2(WN[2 * m],     q.x, aN0);
                aN1 = ffma2(WN[2 * m + 1], q.y, aN1);
            }
            ull sR = add2(aR0, aR1);
            ull sZ = add2(aZ0, aZ1);
            ull sN = add2(aN0, aN1);
            float rl, rh, zl, zh, nl, nh;
            upk2(sR, rl, rh); upk2(sZ, zl, zh); upk2(sN, nl, nh);

            float r = fsigmoid(xr[s] + (rl + rh));
            float z = fsigmoid(xz[s] + (zl + zh));
            float n = ftanh(fmaf(r, nl + nh, xn[s]));
            float hnew = fmaf(z, h - n, n);        // (1-z)*n + z*h

            if (act) hsm[w][(s + 1) & 1][j] = hnew;
            __syncwarp();

            if (act) outp[(size_t)(g * TS_ + s) * H_ + j] = fmaf(pw, hnew, pb);
            h = hnew;
        }

        // ---- publish prefetched group g+1 into the other buffer ----
        {
            float4* dst = ((g + 1) & 1) ? xbuf1 : xbuf0;
            dst[c0] = pf0;
            if (has1) dst[c1] = pf1;
        }
        __syncwarp();
    }

    if (act) out_hidden[(size_t)b * H_ + j] = h;
}

// ============================================================================
extern "C" void kernel_launch(void* const* d_in, const int* in_sizes, int n_in,
                              void* d_out, int out_size) {
    const float* task = (const float*)d_in[0];  // (2048,512,58)
    const float* Wih  = (const float*)d_in[1];  // (69,58)
    const float* Whh  = (const float*)d_in[2];  // (69,23)
    const float* bih  = (const float*)d_in[3];  // (69)
    const float* bhh  = (const float*)d_in[4];  // (69)
    const float* piw  = (const float*)d_in[5];  // (23)
    const float* pib  = (const float*)d_in[6];  // (23)

    float* out = (float*)d_out;
    float* action = out;                                  // B*T*H
    float* hidden = out + (size_t)B_ * T_ * H_;           // B*H

    fused_gru_kernel<<<B_ / 4, 128>>>(task, Wih, Whh, bih, bhh, piw, pib,
                                      action, hidden);
}